// round 2
// baseline (speedup 1.0000x reference)
#include <cuda_runtime.h>
#include <cuda_bf16.h>
#include <cstdint>

constexpr int NN = 100000;    // nodes
constexpr int NE = 3200000;   // edges
constexpr int CIN = 512;
constexpr int CH  = 40;
constexpr int COUT = 20;

// Scratch (__device__ globals: allocation-free per harness rules)
__device__ __align__(16) float g_h1[(size_t)NN * CH];
__device__ __align__(16) float g_acc1[(size_t)NN * CH];
__device__ __align__(16) float g_h2[(size_t)NN * COUT];
__device__ __align__(16) float g_acc2[(size_t)NN * COUT];
__device__ float g_dinv[NN];
__device__ int   g_deg[NN];

// ---------------------------------------------------------------------------
// helpers
// ---------------------------------------------------------------------------
__device__ __forceinline__ unsigned long long ffma2(unsigned long long a,
                                                    unsigned long long b,
                                                    unsigned long long c) {
    unsigned long long d;
    asm("fma.rn.f32x2 %0, %1, %2, %3;" : "=l"(d) : "l"(a), "l"(b), "l"(c));
    return d;
}

__device__ __forceinline__ void red_add_v4(float* p, float4 v) {
    asm volatile("red.global.add.v4.f32 [%0], {%1, %2, %3, %4};"
                 :: "l"(p), "f"(v.x), "f"(v.y), "f"(v.z), "f"(v.w)
                 : "memory");
}

__device__ __forceinline__ void cp_async16(uint32_t dst_smem, const void* src,
                                           int src_bytes) {
    asm volatile("cp.async.cg.shared.global [%0], [%1], 16, %2;"
                 :: "r"(dst_smem), "l"(src), "r"(src_bytes));
}
__device__ __forceinline__ void cp_commit() {
    asm volatile("cp.async.commit_group;");
}
template <int N>
__device__ __forceinline__ void cp_wait() {
    asm volatile("cp.async.wait_group %0;" :: "n"(N));
}

__device__ __forceinline__ uint32_t smem_u32(const void* p) {
    uint32_t a;
    asm("{ .reg .u64 t; cvta.to.shared.u64 t, %1; cvt.u32.u64 %0, t; }"
        : "=r"(a) : "l"(p));
    return a;
}

// ---------------------------------------------------------------------------
// degree / dinv
// ---------------------------------------------------------------------------
__global__ void k_deg_init() {
    int i = blockIdx.x * 256 + threadIdx.x;
    if (i < NN) g_deg[i] = 1;  // self-loop
}
__global__ void k_deg_count(const int* __restrict__ ei) {
    int e = blockIdx.x * 256 + threadIdx.x;
    if (e < NE) atomicAdd(&g_deg[ei[NE + e]], 1);
}
__global__ void k_dinv() {
    int i = blockIdx.x * 256 + threadIdx.x;
    if (i < NN) g_dinv[i] = rsqrtf((float)g_deg[i]);
}

// ---------------------------------------------------------------------------
// GEMM1: hs1 = dinv * (x @ W1).  M=100000, K=512, N=40.
// 64 threads/block, 128 rows/block. Thread: 8 rows x 10 cols (5 f32x2 pairs).
// Col-packed accumulators => W loads are natural f32x2 pairs (no duplication).
// x staged via cp.async into swizzled smem ([row][32] with chunk rotation by
// row>>3, making the 8-rows-apart LDS.32 pattern bank-conflict-free).
// ---------------------------------------------------------------------------
constexpr int KT = 16;               // k per tile
constexpr int NT = CIN / KT;         // 32 tiles
constexpr int RT = 128;              // rows per block
constexpr int XROW = 32;             // padded floats per row in xs

__global__ __launch_bounds__(64) void k_gemm1(const float* __restrict__ x,
                                              const float* __restrict__ W1) {
    __shared__ __align__(16) float xs[2][RT * XROW];   // 2 x 16 KB
    __shared__ __align__(16) float ws[2][KT * CH];     // 2 x 2.5 KB

    const int tid = threadIdx.x;
    const int rp = tid >> 2;          // 0..15 : rows rp*8 .. rp*8+7
    const int ct = tid & 3;           // 0..3  : cols ct*10 .. ct*10+9
    const int row0 = blockIdx.x * RT;

    const uint32_t xs_b[2] = { smem_u32(&xs[0][0]), smem_u32(&xs[1][0]) };
    const uint32_t ws_b[2] = { smem_u32(&ws[0][0]), smem_u32(&ws[1][0]) };

    auto stage = [&](int t) {
        int kt = t * KT;
        int buf = t & 1;
        // x tile: 128 rows x 16 k = 512 x 16B chunks, 8 per thread
#pragma unroll
        for (int i = 0; i < 8; i++) {
            int idx = tid + 64 * i;         // 0..511
            int r = idx >> 2;
            int q = idx & 3;
            int gr = row0 + r;
            const float* src = x + (size_t)gr * CIN + kt + q * 4;
            uint32_t dst = xs_b[buf] + (uint32_t)(r * XROW + 4 * ((q + (r >> 3)) & 7)) * 4u;
            cp_async16(dst, src, (gr < NN) ? 16 : 0);
        }
        // w tile: 16 x 40 floats = 160 chunks (contiguous in W1)
#pragma unroll
        for (int i = 0; i < 3; i++) {
            int idx = tid + 64 * i;
            if (idx < 160)
                cp_async16(ws_b[buf] + (uint32_t)idx * 16u, W1 + kt * CH + idx * 4, 16);
        }
    };

    unsigned long long acc[8][5];
#pragma unroll
    for (int r = 0; r < 8; r++)
#pragma unroll
        for (int j = 0; j < 5; j++) acc[r][j] = 0ull;

    stage(0);
    cp_commit();

    for (int t = 0; t < NT; t++) {
        int buf = t & 1;
        if (t + 1 < NT) {
            stage(t + 1);
            cp_commit();
            cp_wait<1>();
        } else {
            cp_wait<0>();
        }
        __syncthreads();

        const float* xsb = &xs[buf][0];
        const float* wsb = &ws[buf][0];
#pragma unroll
        for (int k = 0; k < KT; k++) {
            unsigned long long wv[5];
            const float* wk = wsb + k * CH + ct * 10;
#pragma unroll
            for (int j = 0; j < 5; j++)
                wv[j] = *(const unsigned long long*)(wk + 2 * j);
            int pos = 4 * (((k >> 2) + rp) & 7) + (k & 3);
#pragma unroll
            for (int r = 0; r < 8; r++) {
                float xv = xsb[(rp * 8 + r) * XROW + pos];
                unsigned long long xd;
                asm("mov.b64 %0, {%1, %1};" : "=l"(xd) : "f"(xv));
#pragma unroll
                for (int j = 0; j < 5; j++)
                    acc[r][j] = ffma2(xd, wv[j], acc[r][j]);
            }
        }
        __syncthreads();
    }

    // epilogue: scale by dinv, write message buffer + accumulator (self-loop)
#pragma unroll
    for (int r = 0; r < 8; r++) {
        int gr = row0 + rp * 8 + r;
        if (gr < NN) {
            float dv = g_dinv[gr];
#pragma unroll
            for (int j = 0; j < 5; j++) {
                unsigned long long a = acc[r][j];
                float lo = __uint_as_float((unsigned)a) * dv;
                float hi = __uint_as_float((unsigned)(a >> 32)) * dv;
                int c = ct * 10 + 2 * j;
                float2 v = make_float2(lo, hi);
                *(float2*)&g_h1[(size_t)gr * CH + c] = v;
                *(float2*)&g_acc1[(size_t)gr * CH + c] = v;
            }
        }
    }
}

// ---------------------------------------------------------------------------
// Aggregation layer 1: 2 threads per edge, 5 x (float4 gather + red.v4) each
// ---------------------------------------------------------------------------
__global__ void k_agg1(const int* __restrict__ ei) {
    unsigned t = blockIdx.x * 256u + threadIdx.x;
    unsigned e = t >> 1;
    if (e >= (unsigned)NE) return;
    unsigned half = t & 1u;
    int s = __ldg(&ei[e]);
    int d = __ldg(&ei[NE + e]);
    const float4* src = (const float4*)&g_h1[(size_t)s * CH + half * 20];
    float4* dst = (float4*)&g_acc1[(size_t)d * CH + half * 20];
    float4 v0 = src[0], v1 = src[1], v2 = src[2], v3 = src[3], v4 = src[4];
    red_add_v4((float*)(dst + 0), v0);
    red_add_v4((float*)(dst + 1), v1);
    red_add_v4((float*)(dst + 2), v2);
    red_add_v4((float*)(dst + 3), v3);
    red_add_v4((float*)(dst + 4), v4);
}

// ---------------------------------------------------------------------------
// Layer-1 finish + GEMM2: r = relu(dinv*acc1 + b1); hs2 = dinv * (r @ W2)
// ---------------------------------------------------------------------------
__global__ __launch_bounds__(128) void k_layer2(const float* __restrict__ W2,
                                                const float* __restrict__ b1) {
    __shared__ float w2s[CH * COUT];
    __shared__ float b1s[CH];
    int tid = threadIdx.x;
    for (int i = tid; i < CH * COUT; i += 128) w2s[i] = W2[i];
    if (tid < CH) b1s[tid] = b1[tid];
    __syncthreads();

    int r = blockIdx.x * 128 + tid;
    if (r >= NN) return;
    float dv = g_dinv[r];

    float rv[CH];
#pragma unroll
    for (int q = 0; q < 10; q++) {
        float4 v = *(const float4*)&g_acc1[(size_t)r * CH + q * 4];
        rv[4 * q + 0] = fmaxf(dv * v.x + b1s[4 * q + 0], 0.f);
        rv[4 * q + 1] = fmaxf(dv * v.y + b1s[4 * q + 1], 0.f);
        rv[4 * q + 2] = fmaxf(dv * v.z + b1s[4 * q + 2], 0.f);
        rv[4 * q + 3] = fmaxf(dv * v.w + b1s[4 * q + 3], 0.f);
    }

    float acc[COUT];
#pragma unroll
    for (int c = 0; c < COUT; c++) acc[c] = 0.f;
#pragma unroll
    for (int k = 0; k < CH; k++) {
        float xv = rv[k];
#pragma unroll
        for (int c = 0; c < COUT; c++)
            acc[c] = fmaf(xv, w2s[k * COUT + c], acc[c]);
    }

#pragma unroll
    for (int q = 0; q < 5; q++) {
        float4 o = make_float4(dv * acc[4 * q + 0], dv * acc[4 * q + 1],
                               dv * acc[4 * q + 2], dv * acc[4 * q + 3]);
        *(float4*)&g_h2[(size_t)r * COUT + 4 * q] = o;
        *(float4*)&g_acc2[(size_t)r * COUT + 4 * q] = o;
    }
}

// ---------------------------------------------------------------------------
// Aggregation layer 2: 1 thread per edge, 5 x (float4 gather + red.v4)
// ---------------------------------------------------------------------------
__global__ void k_agg2(const int* __restrict__ ei) {
    unsigned e = blockIdx.x * 256u + threadIdx.x;
    if (e >= (unsigned)NE) return;
    int s = __ldg(&ei[e]);
    int d = __ldg(&ei[NE + e]);
    const float4* src = (const float4*)&g_h2[(size_t)s * COUT];
    float4* dst = (float4*)&g_acc2[(size_t)d * COUT];
    float4 v0 = src[0], v1 = src[1], v2 = src[2], v3 = src[3], v4 = src[4];
    red_add_v4((float*)(dst + 0), v0);
    red_add_v4((float*)(dst + 1), v1);
    red_add_v4((float*)(dst + 2), v2);
    red_add_v4((float*)(dst + 3), v3);
    red_add_v4((float*)(dst + 4), v4);
}

// ---------------------------------------------------------------------------
// Final: out = dinv * acc2 + b2
// ---------------------------------------------------------------------------
__global__ void k_final(float* __restrict__ out, const float* __restrict__ b2) {
    int idx = blockIdx.x * 256 + threadIdx.x;
    if (idx >= NN * COUT) return;
    int r = idx / COUT;
    int c = idx - r * COUT;
    out[idx] = g_dinv[r] * g_acc2[idx] + __ldg(&b2[c]);
}

// ---------------------------------------------------------------------------
extern "C" void kernel_launch(void* const* d_in, const int* in_sizes, int n_in,
                              void* d_out, int out_size) {
    const float* x  = (const float*)d_in[0];
    const int*   ei = (const int*)d_in[1];
    const float* W1 = (const float*)d_in[2];
    const float* b1 = (const float*)d_in[3];
    const float* W2 = (const float*)d_in[4];
    const float* b2 = (const float*)d_in[5];
    float* out = (float*)d_out;

    k_deg_init<<<(NN + 255) / 256, 256>>>();
    k_deg_count<<<(NE + 255) / 256, 256>>>(ei);
    k_dinv<<<(NN + 255) / 256, 256>>>();
    k_gemm1<<<(NN + RT - 1) / RT, 64>>>(x, W1);
    {
        long long th = (long long)NE * 2;
        k_agg1<<<(unsigned)((th + 255) / 256), 256>>>(ei);
    }
    k_layer2<<<(NN + 127) / 128, 128>>>(W2, b1);
    k_agg2<<<(NE + 255) / 256, 256>>>(ei);
    k_final<<<(NN * COUT + 255) / 256, 256>>>(out, b2);
}

// round 5
// speedup vs baseline: 1.1908x; 1.1908x over previous
#include <cuda_runtime.h>
#include <cuda_bf16.h>
#include <cstdint>

constexpr int NN = 100000;    // nodes
constexpr int NE = 3200000;   // edges
constexpr int CIN = 512;
constexpr int CH  = 40;
constexpr int COUT = 20;

// Scratch (__device__ globals: allocation-free per harness rules)
__device__ __align__(16) float g_h1[(size_t)NN * CH];
__device__ __align__(16) float g_acc1[(size_t)NN * CH];
__device__ __align__(16) float g_h2[(size_t)NN * COUT];
__device__ __align__(16) float g_acc2[(size_t)NN * COUT];
__device__ float g_dinv[NN];
__device__ int   g_deg[NN];

// ---------------------------------------------------------------------------
// helpers
// ---------------------------------------------------------------------------
__device__ __forceinline__ unsigned long long ffma2(unsigned long long a,
                                                    unsigned long long b,
                                                    unsigned long long c) {
    unsigned long long d;
    asm("fma.rn.f32x2 %0, %1, %2, %3;" : "=l"(d) : "l"(a), "l"(b), "l"(c));
    return d;
}

__device__ __forceinline__ void red_add_v4(float* p, float4 v) {
    asm volatile("red.global.add.v4.f32 [%0], {%1, %2, %3, %4};"
                 :: "l"(p), "f"(v.x), "f"(v.y), "f"(v.z), "f"(v.w)
                 : "memory");
}

__device__ __forceinline__ void cp_async16(uint32_t dst_smem, const void* src,
                                           int src_bytes) {
    asm volatile("cp.async.cg.shared.global [%0], [%1], 16, %2;"
                 :: "r"(dst_smem), "l"(src), "r"(src_bytes));
}
__device__ __forceinline__ void cp_commit() {
    asm volatile("cp.async.commit_group;");
}
template <int N>
__device__ __forceinline__ void cp_wait() {
    asm volatile("cp.async.wait_group %0;" :: "n"(N));
}

__device__ __forceinline__ uint32_t smem_u32(const void* p) {
    uint32_t a;
    asm("{ .reg .u64 t; cvta.to.shared.u64 t, %1; cvt.u32.u64 %0, t; }"
        : "=r"(a) : "l"(p));
    return a;
}

// ---------------------------------------------------------------------------
// degree / dinv
// ---------------------------------------------------------------------------
__global__ void k_deg_init() {
    int i = blockIdx.x * 256 + threadIdx.x;
    if (i < NN) g_deg[i] = 1;  // self-loop
}
__global__ void k_deg_count(const int* __restrict__ ei) {
    int e = blockIdx.x * 256 + threadIdx.x;
    if (e < NE) atomicAdd(&g_deg[ei[NE + e]], 1);
}
__global__ void k_dinv() {
    int i = blockIdx.x * 256 + threadIdx.x;
    if (i < NN) g_dinv[i] = rsqrtf((float)g_deg[i]);
}

// ---------------------------------------------------------------------------
// GEMM1: hs1 = dinv * (x @ W1).  M=100000, K=512, N=40.
// 128 threads/block, 128 rows/block. Thread: 4 rows (strided 32) x 10 cols
// (5 f32x2 pairs). XROW=20-float row stride: rp*20 mod 32 spans 8 distinct
// banks -> conflict-free scalar x reads; 16B-aligned for cp.async.
// ---------------------------------------------------------------------------
constexpr int KT = 16;               // k per tile
constexpr int NT = CIN / KT;         // 32 tiles
constexpr int RT = 128;              // rows per block
constexpr int XROW = 20;             // padded floats per row in xs

__global__ __launch_bounds__(128) void k_gemm1(const float* __restrict__ x,
                                               const float* __restrict__ W1) {
    __shared__ __align__(16) float xs[2][RT * XROW];   // 2 x 10 KB
    __shared__ __align__(16) float ws[2][KT * CH];     // 2 x 2.5 KB

    const int tid = threadIdx.x;
    const int rp = tid >> 2;          // 0..31 : rows rp, rp+32, rp+64, rp+96
    const int ct = tid & 3;           // 0..3  : cols ct*10 .. ct*10+9
    const int row0 = blockIdx.x * RT;

    const uint32_t xs_b[2] = { smem_u32(&xs[0][0]), smem_u32(&xs[1][0]) };
    const uint32_t ws_b[2] = { smem_u32(&ws[0][0]), smem_u32(&ws[1][0]) };

    auto stage = [&](int t) {
        int kt = t * KT;
        int buf = t & 1;
        // x tile: 128 rows x 4 chunks(16B) = 512 chunks, 4 per thread
#pragma unroll
        for (int i = 0; i < 4; i++) {
            int idx = tid + 128 * i;        // 0..511
            int r = idx >> 2;
            int q = idx & 3;
            int gr = row0 + r;
            const float* src = x + (size_t)gr * CIN + kt + q * 4;
            uint32_t dst = xs_b[buf] + (uint32_t)(r * XROW + q * 4) * 4u;
            cp_async16(dst, src, (gr < NN) ? 16 : 0);
        }
        // w tile: 16 x 40 floats = 160 chunks of 16B (contiguous in W1)
#pragma unroll
        for (int i = 0; i < 2; i++) {
            int idx = tid + 128 * i;
            if (idx < 160)
                cp_async16(ws_b[buf] + (uint32_t)idx * 16u, W1 + kt * CH + idx * 4, 16);
        }
    };

    unsigned long long acc[4][5];
#pragma unroll
    for (int i = 0; i < 4; i++)
#pragma unroll
        for (int j = 0; j < 5; j++) acc[i][j] = 0ull;

    stage(0);
    cp_commit();

    for (int t = 0; t < NT; t++) {
        int buf = t & 1;
        if (t + 1 < NT) {
            stage(t + 1);
            cp_commit();
            cp_wait<1>();
        } else {
            cp_wait<0>();
        }
        __syncthreads();

        const float* xsb = &xs[buf][0];
        const float* wsb = &ws[buf][0];
#pragma unroll
        for (int k = 0; k < KT; k++) {
            unsigned long long wv[5];
            const float* wk = wsb + k * CH + ct * 10;
#pragma unroll
            for (int j = 0; j < 5; j++)
                wv[j] = *(const unsigned long long*)(wk + 2 * j);
#pragma unroll
            for (int i = 0; i < 4; i++) {
                float xv = xsb[(i * 32 + rp) * XROW + k];
                unsigned long long xd;
                asm("mov.b64 %0, {%1, %1};" : "=l"(xd) : "f"(xv));
#pragma unroll
                for (int j = 0; j < 5; j++)
                    acc[i][j] = ffma2(xd, wv[j], acc[i][j]);
            }
        }
        __syncthreads();
    }

    // epilogue: scale by dinv, write message buffer + accumulator (self-loop)
#pragma unroll
    for (int i = 0; i < 4; i++) {
        int gr = row0 + i * 32 + rp;
        if (gr < NN) {
            float dv = g_dinv[gr];
#pragma unroll
            for (int j = 0; j < 5; j++) {
                unsigned long long a = acc[i][j];
                float lo = __uint_as_float((unsigned)a) * dv;
                float hi = __uint_as_float((unsigned)(a >> 32)) * dv;
                int c = ct * 10 + 2 * j;
                float2 v = make_float2(lo, hi);
                *(float2*)&g_h1[(size_t)gr * CH + c] = v;
                *(float2*)&g_acc1[(size_t)gr * CH + c] = v;
            }
        }
    }
}

// ---------------------------------------------------------------------------
// Aggregation layer 1: 10 threads per edge (coalesced 160B per edge)
// ---------------------------------------------------------------------------
__global__ void k_agg1(const int* __restrict__ ei) {
    unsigned t = blockIdx.x * 256u + threadIdx.x;
    unsigned e = t / 10u;
    if (e >= (unsigned)NE) return;
    unsigned j = t - e * 10u;
    int s = __ldg(&ei[e]);
    int d = __ldg(&ei[NE + e]);
    float4 v = *(const float4*)&g_h1[(size_t)s * CH + j * 4];
    red_add_v4(&g_acc1[(size_t)d * CH + j * 4], v);
}

// ---------------------------------------------------------------------------
// Layer-1 finish + GEMM2: r = relu(dinv*acc1 + b1); hs2 = dinv * (r @ W2)
// ---------------------------------------------------------------------------
__global__ __launch_bounds__(128) void k_layer2(const float* __restrict__ W2,
                                                const float* __restrict__ b1) {
    __shared__ float w2s[CH * COUT];
    __shared__ float b1s[CH];
    int tid = threadIdx.x;
    for (int i = tid; i < CH * COUT; i += 128) w2s[i] = W2[i];
    if (tid < CH) b1s[tid] = b1[tid];
    __syncthreads();

    int r = blockIdx.x * 128 + tid;
    if (r >= NN) return;
    float dv = g_dinv[r];

    float rv[CH];
#pragma unroll
    for (int q = 0; q < 10; q++) {
        float4 v = *(const float4*)&g_acc1[(size_t)r * CH + q * 4];
        rv[4 * q + 0] = fmaxf(dv * v.x + b1s[4 * q + 0], 0.f);
        rv[4 * q + 1] = fmaxf(dv * v.y + b1s[4 * q + 1], 0.f);
        rv[4 * q + 2] = fmaxf(dv * v.z + b1s[4 * q + 2], 0.f);
        rv[4 * q + 3] = fmaxf(dv * v.w + b1s[4 * q + 3], 0.f);
    }

    float acc[COUT];
#pragma unroll
    for (int c = 0; c < COUT; c++) acc[c] = 0.f;
#pragma unroll
    for (int k = 0; k < CH; k++) {
        float xv = rv[k];
#pragma unroll
        for (int c = 0; c < COUT; c++)
            acc[c] = fmaf(xv, w2s[k * COUT + c], acc[c]);
    }

#pragma unroll
    for (int q = 0; q < 5; q++) {
        float4 o = make_float4(dv * acc[4 * q + 0], dv * acc[4 * q + 1],
                               dv * acc[4 * q + 2], dv * acc[4 * q + 3]);
        *(float4*)&g_h2[(size_t)r * COUT + 4 * q] = o;
        *(float4*)&g_acc2[(size_t)r * COUT + 4 * q] = o;
    }
}

// ---------------------------------------------------------------------------
// Aggregation layer 2: 5 threads per edge (coalesced 80B per edge)
// ---------------------------------------------------------------------------
__global__ void k_agg2(const int* __restrict__ ei) {
    unsigned t = blockIdx.x * 256u + threadIdx.x;
    unsigned e = t / 5u;
    if (e >= (unsigned)NE) return;
    unsigned j = t - e * 5u;
    int s = __ldg(&ei[e]);
    int d = __ldg(&ei[NE + e]);
    float4 v = *(const float4*)&g_h2[(size_t)s * COUT + j * 4];
    red_add_v4(&g_acc2[(size_t)d * COUT + j * 4], v);
}

// ---------------------------------------------------------------------------
// Final: out = dinv * acc2 + b2
// ---------------------------------------------------------------------------
__global__ void k_final(float* __restrict__ out, const float* __restrict__ b2) {
    int idx = blockIdx.x * 256 + threadIdx.x;
    if (idx >= NN * COUT) return;
    int r = idx / COUT;
    int c = idx - r * COUT;
    out[idx] = g_dinv[r] * g_acc2[idx] + __ldg(&b2[c]);
}

// ---------------------------------------------------------------------------
extern "C" void kernel_launch(void* const* d_in, const int* in_sizes, int n_in,
                              void* d_out, int out_size) {
    const float* x  = (const float*)d_in[0];
    const int*   ei = (const int*)d_in[1];
    const float* W1 = (const float*)d_in[2];
    const float* b1 = (const float*)d_in[3];
    const float* W2 = (const float*)d_in[4];
    const float* b2 = (const float*)d_in[5];
    float* out = (float*)d_out;

    k_deg_init<<<(NN + 255) / 256, 256>>>();
    k_deg_count<<<(NE + 255) / 256, 256>>>(ei);
    k_dinv<<<(NN + 255) / 256, 256>>>();
    k_gemm1<<<(NN + RT - 1) / RT, 128>>>(x, W1);
    {
        long long th = (long long)NE * 10;
        k_agg1<<<(unsigned)((th + 255) / 256), 256>>>(ei);
    }
    k_layer2<<<(NN + 127) / 128, 128>>>(W2, b1);
    {
        long long th = (long long)NE * 5;
        k_agg2<<<(unsigned)((th + 255) / 256), 256>>>(ei);
    }
    k_final<<<(NN * COUT + 255) / 256, 256>>>(out, b2);
}